// round 15
// baseline (speedup 1.0000x reference)
#include <cuda_runtime.h>
#include <cuda_bf16.h>

#define NMAX 100000
#define NPAD 100128          // NMAX rounded up to 128-row block
#define EMAX 1600000
#define DEGMAX 64

// ---------------- scratch (device globals) -----------------------------------
__device__ int      g_cnt[NMAX];
__device__ float    g_dinv[NMAX];
__device__ int      g_srcfix[(size_t)NMAX * DEGMAX];  // per-dst src lists
__device__ float    g_h1[(size_t)NPAD * 64];          // layer1 features (scaled after k_dinvscale)
__device__ unsigned g_a1h[(size_t)NPAD * 32];         // a1 bf16-hi packed pairs
__device__ unsigned g_a1l[(size_t)NPAD * 32];         // a1 bf16-lo packed pairs
__device__ float    g_h2[(size_t)NPAD * 32];          // dinv-scaled layer2 features
__device__ uint4    g_wfrag[4096];                    // W1 bf16 fragments
__device__ uint4    g_w2frag[512];                    // W2 bf16 fragments

// ---------------- bf16 helpers -------------------------------------------------
__device__ __forceinline__ unsigned pack_bf16(__nv_bfloat16 lo, __nv_bfloat16 hi) {
    __nv_bfloat162 p; p.x = lo; p.y = hi;
    return *(unsigned*)&p;
}
__device__ __forceinline__ void split_bf16(float f, __nv_bfloat16& h, __nv_bfloat16& l) {
    h = __float2bfloat16_rn(f);
    l = __float2bfloat16_rn(f - __bfloat162float(h));
}
__device__ __forceinline__ void mma_bf16(float* d, const unsigned* a, unsigned b0, unsigned b1) {
    asm volatile(
        "mma.sync.aligned.m16n8k16.row.col.f32.bf16.bf16.f32 "
        "{%0,%1,%2,%3}, {%4,%5,%6,%7}, {%8,%9}, {%0,%1,%2,%3};"
        : "+f"(d[0]), "+f"(d[1]), "+f"(d[2]), "+f"(d[3])
        : "r"(a[0]), "r"(a[1]), "r"(a[2]), "r"(a[3]), "r"(b0), "r"(b1));
}

// ---- prep: W1/W2 bf16 hi/lo fragments (validated layouts) ----------------------
__global__ void k_prepw(const float* __restrict__ W1, const float* __restrict__ W2) {
    int i = blockIdx.x * blockDim.x + threadIdx.x;
    if (i < 4096) {   // W1 fragments
        int lane = i & 31;
        int t    = (i >> 5) & 7;
        int ks   = i >> 8;
        int qid = lane & 3, grp = lane >> 2;
        int col = t * 8 + grp;
        int k0 = ks * 16 + qid * 2;
        float f00 = W1[k0 * 64 + col],       f01 = W1[(k0 + 1) * 64 + col];
        float f10 = W1[(k0 + 8) * 64 + col], f11 = W1[(k0 + 9) * 64 + col];
        __nv_bfloat16 h00, l00, h01, l01, h10, l10, h11, l11;
        split_bf16(f00, h00, l00); split_bf16(f01, h01, l01);
        split_bf16(f10, h10, l10); split_bf16(f11, h11, l11);
        g_wfrag[i] = make_uint4(pack_bf16(h00, h01), pack_bf16(h10, h11),
                                pack_bf16(l00, l01), pack_bf16(l10, l11));
    }
    if (i < 512) {    // W2 fragments
        int lane = i & 31;
        int t    = (i >> 5) & 3;
        int ks   = i >> 7;
        int qid = lane & 3, grp = lane >> 2;
        int col = t * 8 + grp;
        int k0 = ks * 16 + qid * 2;
        float f00 = W2[k0 * 32 + col],       f01 = W2[(k0 + 1) * 32 + col];
        float f10 = W2[(k0 + 8) * 32 + col], f11 = W2[(k0 + 9) * 32 + col];
        __nv_bfloat16 h00, l00, h01, l01, h10, l10, h11, l11;
        split_bf16(f00, h00, l00); split_bf16(f01, h01, l01);
        split_bf16(f10, h10, l10); split_bf16(f11, h11, l11);
        g_w2frag[i] = make_uint4(pack_bf16(h00, h01), pack_bf16(h10, h11),
                                 pack_bf16(l00, l01), pack_bf16(l10, l11));
    }
}

// ---- MEGA: edge-bucket fill (blocks < fb, scheduled FIRST) + gemm1 tiles -------
// fill: atomic degree + scatter src. gemm1: R14 form (regs<=64, 4 CTAs/SM),
// UNSCALED epilogue (dinv applied by k_dinvscale) -> no dependency on fill.
// Fill's LSU/L2-atomic work hides under gemm1's tensor/L1 waves.
#define XS2 20
__global__ __launch_bounds__(256, 4) void k_mega(const float* __restrict__ x, int n,
                                                 const int* __restrict__ src,
                                                 const int* __restrict__ dst, int e,
                                                 int fb) {
    __shared__ unsigned xhi[64 * XS2];
    __shared__ unsigned xlo[64 * XS2];
    int tid = threadIdx.x;

    if (blockIdx.x < fb) {             // ---------- fill path ----------
        int i = blockIdx.x * 256 + tid;
        if (i < e) {
            int s = src[i], d = dst[i];
            int pos = atomicAdd(&g_cnt[d], 1);
            if (pos < DEGMAX) g_srcfix[(size_t)d * DEGMAX + pos] = s;
        }
        return;
    }

    // ---------- gemm1 path (R14 proven form, unscaled output) ----------
    int lane = tid & 31, warp = tid >> 5;
    int node0 = (blockIdx.x - fb) * 64;
    int grp = lane >> 2, qid = lane & 3;
    int rg = warp >> 1, cg = warp & 1;

    float d[4][4];
#pragma unroll
    for (int t = 0; t < 4; t++) { d[t][0] = d[t][1] = d[t][2] = d[t][3] = 0.f; }

    int srow = tid >> 2;
    int sq   = tid & 3;

    for (int kc = 0; kc < 8; kc++) {            // K chunk of 32
        __syncthreads();
        {
            float4 v0 = make_float4(0.f, 0.f, 0.f, 0.f);
            float4 v1 = make_float4(0.f, 0.f, 0.f, 0.f);
            if (node0 + srow < n) {
                const float4* xp = (const float4*)(x + (size_t)(node0 + srow) * 256 + kc * 32 + sq * 8);
                v0 = xp[0]; v1 = xp[1];
            }
            __nv_bfloat16 h0, l0, h1, l1;
            unsigned ph0, ph1, ph2, ph3, pl0, pl1, pl2, pl3;
            split_bf16(v0.x, h0, l0); split_bf16(v0.y, h1, l1);
            ph0 = pack_bf16(h0, h1); pl0 = pack_bf16(l0, l1);
            split_bf16(v0.z, h0, l0); split_bf16(v0.w, h1, l1);
            ph1 = pack_bf16(h0, h1); pl1 = pack_bf16(l0, l1);
            split_bf16(v1.x, h0, l0); split_bf16(v1.y, h1, l1);
            ph2 = pack_bf16(h0, h1); pl2 = pack_bf16(l0, l1);
            split_bf16(v1.z, h0, l0); split_bf16(v1.w, h1, l1);
            ph3 = pack_bf16(h0, h1); pl3 = pack_bf16(l0, l1);
            unsigned base = srow * XS2 + sq * 4;
            *(uint4*)(xhi + base) = make_uint4(ph0, ph1, ph2, ph3);
            *(uint4*)(xlo + base) = make_uint4(pl0, pl1, pl2, pl3);
        }
        __syncthreads();

#pragma unroll
        for (int ksl = 0; ksl < 2; ksl++) {
            int ks = kc * 2 + ksl;
            int r = rg * 16 + grp;
            int cb = ksl * 8;
            unsigned ah[4], al[4];
            ah[0] = xhi[r * XS2 + cb + qid];
            ah[1] = xhi[(r + 8) * XS2 + cb + qid];
            ah[2] = xhi[r * XS2 + cb + qid + 4];
            ah[3] = xhi[(r + 8) * XS2 + cb + qid + 4];
            al[0] = xlo[r * XS2 + cb + qid];
            al[1] = xlo[(r + 8) * XS2 + cb + qid];
            al[2] = xlo[r * XS2 + cb + qid + 4];
            al[3] = xlo[(r + 8) * XS2 + cb + qid + 4];
#pragma unroll
            for (int t = 0; t < 4; t++) {
                int tt = cg * 4 + t;
                uint4 w = __ldg(&g_wfrag[(ks * 8 + tt) * 32 + lane]);
                mma_bf16(d[t], ah, w.x, w.y);
                mma_bf16(d[t], al, w.x, w.y);
                mma_bf16(d[t], ah, w.z, w.w);
            }
        }
    }

    int r0 = node0 + rg * 16 + grp;
#pragma unroll
    for (int t = 0; t < 4; t++) {
        int col = cg * 32 + t * 8 + qid * 2;
        if (r0 < n)     *(float2*)(g_h1 + (size_t)r0 * 64 + col)       = make_float2(d[t][0], d[t][1]);
        if (r0 + 8 < n) *(float2*)(g_h1 + (size_t)(r0 + 8) * 64 + col) = make_float2(d[t][2], d[t][3]);
    }
}

// ---- dinv + scale: g_dinv[i] = rsqrt(cnt+1); h1 row i *= dinv (coalesced) -----
// One warp per row: lane l scales float2 l of the row.
__global__ __launch_bounds__(256) void k_dinvscale(int n) {
    int lane = threadIdx.x & 31;
    int row = (blockIdx.x * blockDim.x + threadIdx.x) >> 5;
    if (row >= n) return;
    float di = rsqrtf((float)(g_cnt[row] + 1));   // +1 self loop
    if (lane == 0) g_dinv[row] = di;
    float2* hp = (float2*)(g_h1 + (size_t)row * 64);
    float2 v = hp[lane];
    hp[lane] = make_float2(di * v.x, di * v.y);
}

// ---- layer 1 aggregation: a1 = relu(dinv*(sum ht1) + b1), stored packed bf16 --
// MLP=16 main loop (proven R10 form).
__global__ __launch_bounds__(256) void k_agg1(const float* __restrict__ b1, int n) {
    int lane = threadIdx.x & 31;
    int node = (blockIdx.x * blockDim.x + threadIdx.x) >> 5;
    if (node >= n) return;

    float di = g_dinv[node];
    float2 acc0 = ((const float2*)(g_h1 + (size_t)node * 64))[lane];  // self loop
    float2 acc1 = make_float2(0.f, 0.f);
    float2 acc2 = make_float2(0.f, 0.f);
    float2 acc3 = make_float2(0.f, 0.f);

    const int* ep = g_srcfix + (size_t)node * DEGMAX;
    int cnt = g_cnt[node];
    if (cnt > DEGMAX) cnt = DEGMAX;
    int k = 0;
    for (; k + 16 <= cnt; k += 16) {
        int4 sa = *(const int4*)(ep + k);
        int4 sb = *(const int4*)(ep + k + 4);
        int4 sc = *(const int4*)(ep + k + 8);
        int4 sd = *(const int4*)(ep + k + 12);
        float2 v0  = ((const float2*)(g_h1 + (size_t)sa.x * 64))[lane];
        float2 v1  = ((const float2*)(g_h1 + (size_t)sa.y * 64))[lane];
        float2 v2  = ((const float2*)(g_h1 + (size_t)sa.z * 64))[lane];
        float2 v3  = ((const float2*)(g_h1 + (size_t)sa.w * 64))[lane];
        float2 v4  = ((const float2*)(g_h1 + (size_t)sb.x * 64))[lane];
        float2 v5  = ((const float2*)(g_h1 + (size_t)sb.y * 64))[lane];
        float2 v6  = ((const float2*)(g_h1 + (size_t)sb.z * 64))[lane];
        float2 v7  = ((const float2*)(g_h1 + (size_t)sb.w * 64))[lane];
        float2 v8  = ((const float2*)(g_h1 + (size_t)sc.x * 64))[lane];
        float2 v9  = ((const float2*)(g_h1 + (size_t)sc.y * 64))[lane];
        float2 v10 = ((const float2*)(g_h1 + (size_t)sc.z * 64))[lane];
        float2 v11 = ((const float2*)(g_h1 + (size_t)sc.w * 64))[lane];
        float2 v12 = ((const float2*)(g_h1 + (size_t)sd.x * 64))[lane];
        float2 v13 = ((const float2*)(g_h1 + (size_t)sd.y * 64))[lane];
        float2 v14 = ((const float2*)(g_h1 + (size_t)sd.z * 64))[lane];
        float2 v15 = ((const float2*)(g_h1 + (size_t)sd.w * 64))[lane];
        acc0.x += v0.x  + v4.x;  acc0.y += v0.y  + v4.y;
        acc1.x += v1.x  + v5.x;  acc1.y += v1.y  + v5.y;
        acc2.x += v2.x  + v6.x;  acc2.y += v2.y  + v6.y;
        acc3.x += v3.x  + v7.x;  acc3.y += v3.y  + v7.y;
        acc0.x += v8.x  + v12.x; acc0.y += v8.y  + v12.y;
        acc1.x += v9.x  + v13.x; acc1.y += v9.y  + v13.y;
        acc2.x += v10.x + v14.x; acc2.y += v10.y + v14.y;
        acc3.x += v11.x + v15.x; acc3.y += v11.y + v15.y;
    }
    for (; k + 8 <= cnt; k += 8) {
        int4 sa = *(const int4*)(ep + k);
        int4 sb = *(const int4*)(ep + k + 4);
        float2 v0 = ((const float2*)(g_h1 + (size_t)sa.x * 64))[lane];
        float2 v1 = ((const float2*)(g_h1 + (size_t)sa.y * 64))[lane];
        float2 v2 = ((const float2*)(g_h1 + (size_t)sa.z * 64))[lane];
        float2 v3 = ((const float2*)(g_h1 + (size_t)sa.w * 64))[lane];
        float2 v4 = ((const float2*)(g_h1 + (size_t)sb.x * 64))[lane];
        float2 v5 = ((const float2*)(g_h1 + (size_t)sb.y * 64))[lane];
        float2 v6 = ((const float2*)(g_h1 + (size_t)sb.z * 64))[lane];
        float2 v7 = ((const float2*)(g_h1 + (size_t)sb.w * 64))[lane];
        acc0.x += v0.x + v4.x; acc0.y += v0.y + v4.y;
        acc1.x += v1.x + v5.x; acc1.y += v1.y + v5.y;
        acc2.x += v2.x + v6.x; acc2.y += v2.y + v6.y;
        acc3.x += v3.x + v7.x; acc3.y += v3.y + v7.y;
    }
    for (; k < cnt; k++) {
        int s = ep[k];
        float2 v = ((const float2*)(g_h1 + (size_t)s * 64))[lane];
        acc0.x += v.x; acc0.y += v.y;
    }
    acc0.x += acc1.x + acc2.x + acc3.x;
    acc0.y += acc1.y + acc2.y + acc3.y;

    float2 bb = ((const float2*)b1)[lane];
    float ax = fmaxf(fmaf(di, acc0.x, bb.x), 0.f);
    float ay = fmaxf(fmaf(di, acc0.y, bb.y), 0.f);

    __nv_bfloat16 hx, lx, hy, ly;
    split_bf16(ax, hx, lx);
    split_bf16(ay, hy, ly);
    g_a1h[(size_t)node * 32 + lane] = pack_bf16(hx, hy);
    g_a1l[(size_t)node * 32 + lane] = pack_bf16(lx, ly);
}

// ---- layer 2 GEMM (tensor): ht2 = dinv * (a1 @ W2), A-frags direct from gmem --
__global__ __launch_bounds__(256) void k_gemm2t(int n) {
    int tid = threadIdx.x, lane = tid & 31, warp = tid >> 5;
    int node0 = blockIdx.x * 128;
    int grp = lane >> 2, qid = lane & 3;
    int r0 = node0 + warp * 16 + grp;

    float d[4][4];
#pragma unroll
    for (int t = 0; t < 4; t++) { d[t][0] = d[t][1] = d[t][2] = d[t][3] = 0.f; }

    const unsigned* ah_base0 = g_a1h + (size_t)r0 * 32;
    const unsigned* ah_base1 = g_a1h + (size_t)(r0 + 8) * 32;
    const unsigned* al_base0 = g_a1l + (size_t)r0 * 32;
    const unsigned* al_base1 = g_a1l + (size_t)(r0 + 8) * 32;

#pragma unroll
    for (int ks = 0; ks < 4; ks++) {
        unsigned ah[4], al[4];
        ah[0] = __ldg(ah_base0 + ks * 8 + qid);
        ah[1] = __ldg(ah_base1 + ks * 8 + qid);
        ah[2] = __ldg(ah_base0 + ks * 8 + qid + 4);
        ah[3] = __ldg(ah_base1 + ks * 8 + qid + 4);
        al[0] = __ldg(al_base0 + ks * 8 + qid);
        al[1] = __ldg(al_base1 + ks * 8 + qid);
        al[2] = __ldg(al_base0 + ks * 8 + qid + 4);
        al[3] = __ldg(al_base1 + ks * 8 + qid + 4);
#pragma unroll
        for (int t = 0; t < 4; t++) {
            uint4 w = __ldg(&g_w2frag[(ks * 4 + t) * 32 + lane]);
            mma_bf16(d[t], ah, w.x, w.y);
            mma_bf16(d[t], al, w.x, w.y);
            mma_bf16(d[t], ah, w.z, w.w);
        }
    }

    float di0 = (r0 < n)     ? g_dinv[r0]     : 0.f;
    float di1 = (r0 + 8 < n) ? g_dinv[r0 + 8] : 0.f;
#pragma unroll
    for (int t = 0; t < 4; t++) {
        int col = t * 8 + qid * 2;
        if (r0 < n)     *(float2*)(g_h2 + (size_t)r0 * 32 + col)       = make_float2(di0 * d[t][0], di0 * d[t][1]);
        if (r0 + 8 < n) *(float2*)(g_h2 + (size_t)(r0 + 8) * 32 + col) = make_float2(di1 * d[t][2], di1 * d[t][3]);
    }
}

// ------- layer 2 agg fused with final linear ------------------------------------
__global__ __launch_bounds__(256) void k_agg2(const float* __restrict__ b2,
                                              const float* __restrict__ Wlin,
                                              const float* __restrict__ blin,
                                              float* __restrict__ out, int n) {
    int lane = threadIdx.x & 31;
    int node = (blockIdx.x * blockDim.x + threadIdx.x) >> 5;
    if (node >= n) return;

    float di = g_dinv[node];
    float acc0 = g_h2[(size_t)node * 32 + lane];   // self loop
    float acc1 = 0.f, acc2 = 0.f, acc3 = 0.f;

    const int* ep = g_srcfix + (size_t)node * DEGMAX;
    int cnt = g_cnt[node];
    if (cnt > DEGMAX) cnt = DEGMAX;
    int k = 0;
    for (; k + 16 <= cnt; k += 16) {
        int4 sa = *(const int4*)(ep + k);
        int4 sb = *(const int4*)(ep + k + 4);
        int4 sc = *(const int4*)(ep + k + 8);
        int4 sd = *(const int4*)(ep + k + 12);
        float v0  = g_h2[(size_t)sa.x * 32 + lane];
        float v1  = g_h2[(size_t)sa.y * 32 + lane];
        float v2  = g_h2[(size_t)sa.z * 32 + lane];
        float v3  = g_h2[(size_t)sa.w * 32 + lane];
        float v4  = g_h2[(size_t)sb.x * 32 + lane];
        float v5  = g_h2[(size_t)sb.y * 32 + lane];
        float v6  = g_h2[(size_t)sb.z * 32 + lane];
        float v7  = g_h2[(size_t)sb.w * 32 + lane];
        float v8  = g_h2[(size_t)sc.x * 32 + lane];
        float v9  = g_h2[(size_t)sc.y * 32 + lane];
        float v10 = g_h2[(size_t)sc.z * 32 + lane];
        float v11 = g_h2[(size_t)sc.w * 32 + lane];
        float v12 = g_h2[(size_t)sd.x * 32 + lane];
        float v13 = g_h2[(size_t)sd.y * 32 + lane];
        float v14 = g_h2[(size_t)sd.z * 32 + lane];
        float v15 = g_h2[(size_t)sd.w * 32 + lane];
        acc0 += v0 + v4 + v8  + v12;
        acc1 += v1 + v5 + v9  + v13;
        acc2 += v2 + v6 + v10 + v14;
        acc3 += v3 + v7 + v11 + v15;
    }
    for (; k + 8 <= cnt; k += 8) {
        int4 sa = *(const int4*)(ep + k);
        int4 sb = *(const int4*)(ep + k + 4);
        float v0 = g_h2[(size_t)sa.x * 32 + lane];
        float v1 = g_h2[(size_t)sa.y * 32 + lane];
        float v2 = g_h2[(size_t)sa.z * 32 + lane];
        float v3 = g_h2[(size_t)sa.w * 32 + lane];
        float v4 = g_h2[(size_t)sb.x * 32 + lane];
        float v5 = g_h2[(size_t)sb.y * 32 + lane];
        float v6 = g_h2[(size_t)sb.z * 32 + lane];
        float v7 = g_h2[(size_t)sb.w * 32 + lane];
        acc0 += v0 + v4; acc1 += v1 + v5; acc2 += v2 + v6; acc3 += v3 + v7;
    }
    for (; k < cnt; k++) {
        acc0 += g_h2[(size_t)ep[k] * 32 + lane];
    }
    acc0 += acc1 + acc2 + acc3;

    float v = fmaxf(fmaf(di, acc0, b2[lane]), 0.f);
    float p = v * Wlin[lane];
#pragma unroll
    for (int off = 16; off > 0; off >>= 1) p += __shfl_xor_sync(0xffffffffu, p, off);
    if (lane == 0) out[node] = p + blin[0];
}

// ---------------- launch -------------------------------------------------------
extern "C" void kernel_launch(void* const* d_in, const int* in_sizes, int n_in,
                              void* d_out, int out_size) {
    const float* x    = (const float*)d_in[0];
    const int*   ei   = (const int*)  d_in[1];
    const float* W1   = (const float*)d_in[2];
    const float* b1   = (const float*)d_in[3];
    const float* W2   = (const float*)d_in[4];
    const float* b2   = (const float*)d_in[5];
    const float* Wlin = (const float*)d_in[6];
    const float* blin = (const float*)d_in[7];
    float* out = (float*)d_out;

    int n = in_sizes[0] / 256;
    int e = in_sizes[1] / 2;
    if (n > NMAX) n = NMAX;
    if (e > EMAX) e = EMAX;
    const int* src = ei;
    const int* dst = ei + e;

    void* cnt_ptr = nullptr;
    cudaGetSymbolAddress(&cnt_ptr, g_cnt);
    cudaMemsetAsync(cnt_ptr, 0, (size_t)n * sizeof(int));

    int fb = (e + 255) / 256;     // fill blocks (scheduled first)
    int g1 = (n + 63) / 64;       // gemm1 blocks

    // ncu window captures kernel slot 4 = k_agg1 (verify unchanged ~45us)
    k_prepw     <<<16, 256>>>(W1, W2);
    k_mega      <<<fb + g1, 256>>>(x, n, src, dst, e, fb);
    k_dinvscale <<<(n + 7) / 8, 256>>>(n);
    k_agg1      <<<(n + 7) / 8, 256>>>(b1, n);
    k_gemm2t    <<<(n + 127) / 128, 256>>>(n);
    k_agg2      <<<(n + 7) / 8, 256>>>(b2, Wlin, blin, out, n);
}

// round 16
// speedup vs baseline: 1.0658x; 1.0658x over previous
#include <cuda_runtime.h>
#include <cuda_bf16.h>
#include <cuda_fp16.h>

#define NMAX 100000
#define NPAD 100128          // NMAX rounded up to 128-row block
#define EMAX 1600000
#define DEGMAX 64

// ---------------- scratch (device globals) -----------------------------------
__device__ int      g_cnt[NMAX];
__device__ float    g_dinv[NMAX];
__device__ int      g_srcfix[(size_t)NMAX * DEGMAX];  // per-dst src lists
__device__ unsigned g_h1[(size_t)NPAD * 32];          // dinv-scaled h1, fp16x2 pairs
__device__ unsigned g_a1h[(size_t)NPAD * 32];         // a1 bf16-hi packed pairs
__device__ unsigned g_a1l[(size_t)NPAD * 32];         // a1 bf16-lo packed pairs
__device__ float    g_h2[(size_t)NPAD * 32];          // dinv-scaled layer2 features
__device__ uint4    g_wfrag[4096];                    // W1 bf16 fragments
__device__ uint4    g_w2frag[512];                    // W2 bf16 fragments

// ---------------- helpers --------------------------------------------------------
__device__ __forceinline__ unsigned pack_bf16(__nv_bfloat16 lo, __nv_bfloat16 hi) {
    __nv_bfloat162 p; p.x = lo; p.y = hi;
    return *(unsigned*)&p;
}
__device__ __forceinline__ void split_bf16(float f, __nv_bfloat16& h, __nv_bfloat16& l) {
    h = __float2bfloat16_rn(f);
    l = __float2bfloat16_rn(f - __bfloat162float(h));
}
__device__ __forceinline__ unsigned pack_f16x2(float a, float b) {
    __half2 h = __float22half2_rn(make_float2(a, b));
    return *(unsigned*)&h;
}
__device__ __forceinline__ float2 unpack_f16x2(unsigned u) {
    __half2 h = *(__half2*)&u;
    return __half22float2(h);
}
__device__ __forceinline__ void mma_bf16(float* d, const unsigned* a, unsigned b0, unsigned b1) {
    asm volatile(
        "mma.sync.aligned.m16n8k16.row.col.f32.bf16.bf16.f32 "
        "{%0,%1,%2,%3}, {%4,%5,%6,%7}, {%8,%9}, {%0,%1,%2,%3};"
        : "+f"(d[0]), "+f"(d[1]), "+f"(d[2]), "+f"(d[3])
        : "r"(a[0]), "r"(a[1]), "r"(a[2]), "r"(a[3]), "r"(b0), "r"(b1));
}

// ---- build: bucket-fill src lists + fused W1/W2 fragment prep (R8 form) --------
__global__ void k_fill_prep(const int* __restrict__ src, const int* __restrict__ dst,
                            int e, const float* __restrict__ W1,
                            const float* __restrict__ W2) {
    int i = blockIdx.x * blockDim.x + threadIdx.x;
    if (i < 4096) {   // W1 fragments (validated layout)
        int lane = i & 31;
        int t    = (i >> 5) & 7;
        int ks   = i >> 8;
        int qid = lane & 3, grp = lane >> 2;
        int col = t * 8 + grp;
        int k0 = ks * 16 + qid * 2;
        float f00 = W1[k0 * 64 + col],       f01 = W1[(k0 + 1) * 64 + col];
        float f10 = W1[(k0 + 8) * 64 + col], f11 = W1[(k0 + 9) * 64 + col];
        __nv_bfloat16 h00, l00, h01, l01, h10, l10, h11, l11;
        split_bf16(f00, h00, l00); split_bf16(f01, h01, l01);
        split_bf16(f10, h10, l10); split_bf16(f11, h11, l11);
        g_wfrag[i] = make_uint4(pack_bf16(h00, h01), pack_bf16(h10, h11),
                                pack_bf16(l00, l01), pack_bf16(l10, l11));
    }
    if (i < 512) {    // W2 fragments
        int lane = i & 31;
        int t    = (i >> 5) & 3;
        int ks   = i >> 7;
        int qid = lane & 3, grp = lane >> 2;
        int col = t * 8 + grp;
        int k0 = ks * 16 + qid * 2;
        float f00 = W2[k0 * 32 + col],       f01 = W2[(k0 + 1) * 32 + col];
        float f10 = W2[(k0 + 8) * 32 + col], f11 = W2[(k0 + 9) * 32 + col];
        __nv_bfloat16 h00, l00, h01, l01, h10, l10, h11, l11;
        split_bf16(f00, h00, l00); split_bf16(f01, h01, l01);
        split_bf16(f10, h10, l10); split_bf16(f11, h11, l11);
        g_w2frag[i] = make_uint4(pack_bf16(h00, h01), pack_bf16(h10, h11),
                                 pack_bf16(l00, l01), pack_bf16(l10, l11));
    }
    if (i < e) {
        int s = src[i], d = dst[i];
        int pos = atomicAdd(&g_cnt[d], 1);
        if (pos < DEGMAX) g_srcfix[(size_t)d * DEGMAX + pos] = s;
    }
}

__global__ void k_dinv(int n) {
    int i = blockIdx.x * blockDim.x + threadIdx.x;
    if (i < n) g_dinv[i] = rsqrtf((float)(g_cnt[i] + 1));  // +1 self loop
}

// ------- layer 1 GEMM: ht1 = dinv * (x @ W1), bf16x3 m16n8k16 (R14 proven) ----
// Epilogue now packs fp16x2 pairs: word j of a row holds features 2j, 2j+1.
#define XS2 20
__global__ __launch_bounds__(256, 4) void k_gemm1(const float* __restrict__ x, int n) {
    __shared__ unsigned xhi[64 * XS2];
    __shared__ unsigned xlo[64 * XS2];
    int tid = threadIdx.x, lane = tid & 31, warp = tid >> 5;
    int node0 = blockIdx.x * 64;
    int grp = lane >> 2, qid = lane & 3;
    int rg = warp >> 1, cg = warp & 1;

    float d[4][4];
#pragma unroll
    for (int t = 0; t < 4; t++) { d[t][0] = d[t][1] = d[t][2] = d[t][3] = 0.f; }

    int srow = tid >> 2;
    int sq   = tid & 3;

    for (int kc = 0; kc < 8; kc++) {            // K chunk of 32
        __syncthreads();
        {
            float4 v0 = make_float4(0.f, 0.f, 0.f, 0.f);
            float4 v1 = make_float4(0.f, 0.f, 0.f, 0.f);
            if (node0 + srow < n) {
                const float4* xp = (const float4*)(x + (size_t)(node0 + srow) * 256 + kc * 32 + sq * 8);
                v0 = xp[0]; v1 = xp[1];
            }
            __nv_bfloat16 h0, l0, h1, l1;
            unsigned ph0, ph1, ph2, ph3, pl0, pl1, pl2, pl3;
            split_bf16(v0.x, h0, l0); split_bf16(v0.y, h1, l1);
            ph0 = pack_bf16(h0, h1); pl0 = pack_bf16(l0, l1);
            split_bf16(v0.z, h0, l0); split_bf16(v0.w, h1, l1);
            ph1 = pack_bf16(h0, h1); pl1 = pack_bf16(l0, l1);
            split_bf16(v1.x, h0, l0); split_bf16(v1.y, h1, l1);
            ph2 = pack_bf16(h0, h1); pl2 = pack_bf16(l0, l1);
            split_bf16(v1.z, h0, l0); split_bf16(v1.w, h1, l1);
            ph3 = pack_bf16(h0, h1); pl3 = pack_bf16(l0, l1);
            unsigned base = srow * XS2 + sq * 4;
            *(uint4*)(xhi + base) = make_uint4(ph0, ph1, ph2, ph3);
            *(uint4*)(xlo + base) = make_uint4(pl0, pl1, pl2, pl3);
        }
        __syncthreads();

#pragma unroll
        for (int ksl = 0; ksl < 2; ksl++) {
            int ks = kc * 2 + ksl;
            int r = rg * 16 + grp;
            int cb = ksl * 8;
            unsigned ah[4], al[4];
            ah[0] = xhi[r * XS2 + cb + qid];
            ah[1] = xhi[(r + 8) * XS2 + cb + qid];
            ah[2] = xhi[r * XS2 + cb + qid + 4];
            ah[3] = xhi[(r + 8) * XS2 + cb + qid + 4];
            al[0] = xlo[r * XS2 + cb + qid];
            al[1] = xlo[(r + 8) * XS2 + cb + qid];
            al[2] = xlo[r * XS2 + cb + qid + 4];
            al[3] = xlo[(r + 8) * XS2 + cb + qid + 4];
#pragma unroll
            for (int t = 0; t < 4; t++) {
                int tt = cg * 4 + t;
                uint4 w = __ldg(&g_wfrag[(ks * 8 + tt) * 32 + lane]);
                mma_bf16(d[t], ah, w.x, w.y);
                mma_bf16(d[t], al, w.x, w.y);
                mma_bf16(d[t], ah, w.z, w.w);
            }
        }
    }

    int r0 = node0 + rg * 16 + grp;
    float di0 = (r0 < n)     ? g_dinv[r0]     : 0.f;
    float di1 = (r0 + 8 < n) ? g_dinv[r0 + 8] : 0.f;
#pragma unroll
    for (int t = 0; t < 4; t++) {
        int j = cg * 16 + t * 4 + qid;   // fp16x2 word index (features 2j, 2j+1)
        if (r0 < n)     g_h1[(size_t)r0 * 32 + j]       = pack_f16x2(di0 * d[t][0], di0 * d[t][1]);
        if (r0 + 8 < n) g_h1[(size_t)(r0 + 8) * 32 + j] = pack_f16x2(di1 * d[t][2], di1 * d[t][3]);
    }
}

// ---- layer 1 aggregation: a1 = relu(dinv*(sum ht1) + b1), stored packed bf16 --
// fp16x2 gather: one u32 per lane per neighbor row (128B/warp, was 256B).
__global__ __launch_bounds__(256) void k_agg1(const float* __restrict__ b1, int n) {
    int lane = threadIdx.x & 31;
    int node = (blockIdx.x * blockDim.x + threadIdx.x) >> 5;
    if (node >= n) return;

    float di = g_dinv[node];
    float2 acc0 = unpack_f16x2(g_h1[(size_t)node * 32 + lane]);  // self loop
    float2 acc1 = make_float2(0.f, 0.f);
    float2 acc2 = make_float2(0.f, 0.f);
    float2 acc3 = make_float2(0.f, 0.f);

    const int* ep = g_srcfix + (size_t)node * DEGMAX;
    int cnt = g_cnt[node];
    if (cnt > DEGMAX) cnt = DEGMAX;
    int k = 0;
    for (; k + 16 <= cnt; k += 16) {
        int4 sa = *(const int4*)(ep + k);
        int4 sb = *(const int4*)(ep + k + 4);
        int4 sc = *(const int4*)(ep + k + 8);
        int4 sd = *(const int4*)(ep + k + 12);
        unsigned u0  = g_h1[(size_t)sa.x * 32 + lane];
        unsigned u1  = g_h1[(size_t)sa.y * 32 + lane];
        unsigned u2  = g_h1[(size_t)sa.z * 32 + lane];
        unsigned u3  = g_h1[(size_t)sa.w * 32 + lane];
        unsigned u4  = g_h1[(size_t)sb.x * 32 + lane];
        unsigned u5  = g_h1[(size_t)sb.y * 32 + lane];
        unsigned u6  = g_h1[(size_t)sb.z * 32 + lane];
        unsigned u7  = g_h1[(size_t)sb.w * 32 + lane];
        unsigned u8  = g_h1[(size_t)sc.x * 32 + lane];
        unsigned u9  = g_h1[(size_t)sc.y * 32 + lane];
        unsigned u10 = g_h1[(size_t)sc.z * 32 + lane];
        unsigned u11 = g_h1[(size_t)sc.w * 32 + lane];
        unsigned u12 = g_h1[(size_t)sd.x * 32 + lane];
        unsigned u13 = g_h1[(size_t)sd.y * 32 + lane];
        unsigned u14 = g_h1[(size_t)sd.z * 32 + lane];
        unsigned u15 = g_h1[(size_t)sd.w * 32 + lane];
        float2 v0  = unpack_f16x2(u0),  v1  = unpack_f16x2(u1);
        float2 v2  = unpack_f16x2(u2),  v3  = unpack_f16x2(u3);
        float2 v4  = unpack_f16x2(u4),  v5  = unpack_f16x2(u5);
        float2 v6  = unpack_f16x2(u6),  v7  = unpack_f16x2(u7);
        float2 v8  = unpack_f16x2(u8),  v9  = unpack_f16x2(u9);
        float2 v10 = unpack_f16x2(u10), v11 = unpack_f16x2(u11);
        float2 v12 = unpack_f16x2(u12), v13 = unpack_f16x2(u13);
        float2 v14 = unpack_f16x2(u14), v15 = unpack_f16x2(u15);
        acc0.x += v0.x  + v4.x;  acc0.y += v0.y  + v4.y;
        acc1.x += v1.x  + v5.x;  acc1.y += v1.y  + v5.y;
        acc2.x += v2.x  + v6.x;  acc2.y += v2.y  + v6.y;
        acc3.x += v3.x  + v7.x;  acc3.y += v3.y  + v7.y;
        acc0.x += v8.x  + v12.x; acc0.y += v8.y  + v12.y;
        acc1.x += v9.x  + v13.x; acc1.y += v9.y  + v13.y;
        acc2.x += v10.x + v14.x; acc2.y += v10.y + v14.y;
        acc3.x += v11.x + v15.x; acc3.y += v11.y + v15.y;
    }
    for (; k + 8 <= cnt; k += 8) {
        int4 sa = *(const int4*)(ep + k);
        int4 sb = *(const int4*)(ep + k + 4);
        float2 v0 = unpack_f16x2(g_h1[(size_t)sa.x * 32 + lane]);
        float2 v1 = unpack_f16x2(g_h1[(size_t)sa.y * 32 + lane]);
        float2 v2 = unpack_f16x2(g_h1[(size_t)sa.z * 32 + lane]);
        float2 v3 = unpack_f16x2(g_h1[(size_t)sa.w * 32 + lane]);
        float2 v4 = unpack_f16x2(g_h1[(size_t)sb.x * 32 + lane]);
        float2 v5 = unpack_f16x2(g_h1[(size_t)sb.y * 32 + lane]);
        float2 v6 = unpack_f16x2(g_h1[(size_t)sb.z * 32 + lane]);
        float2 v7 = unpack_f16x2(g_h1[(size_t)sb.w * 32 + lane]);
        acc0.x += v0.x + v4.x; acc0.y += v0.y + v4.y;
        acc1.x += v1.x + v5.x; acc1.y += v1.y + v5.y;
        acc2.x += v2.x + v6.x; acc2.y += v2.y + v6.y;
        acc3.x += v3.x + v7.x; acc3.y += v3.y + v7.y;
    }
    for (; k < cnt; k++) {
        float2 v = unpack_f16x2(g_h1[(size_t)ep[k] * 32 + lane]);
        acc0.x += v.x; acc0.y += v.y;
    }
    acc0.x += acc1.x + acc2.x + acc3.x;
    acc0.y += acc1.y + acc2.y + acc3.y;

    float2 bb = ((const float2*)b1)[lane];
    float ax = fmaxf(fmaf(di, acc0.x, bb.x), 0.f);
    float ay = fmaxf(fmaf(di, acc0.y, bb.y), 0.f);

    __nv_bfloat16 hx, lx, hy, ly;
    split_bf16(ax, hx, lx);
    split_bf16(ay, hy, ly);
    g_a1h[(size_t)node * 32 + lane] = pack_bf16(hx, hy);
    g_a1l[(size_t)node * 32 + lane] = pack_bf16(lx, ly);
}

// ---- layer 2 GEMM (tensor): ht2 = dinv * (a1 @ W2), A-frags direct from gmem --
__global__ __launch_bounds__(256) void k_gemm2t(int n) {
    int tid = threadIdx.x, lane = tid & 31, warp = tid >> 5;
    int node0 = blockIdx.x * 128;
    int grp = lane >> 2, qid = lane & 3;
    int r0 = node0 + warp * 16 + grp;

    float d[4][4];
#pragma unroll
    for (int t = 0; t < 4; t++) { d[t][0] = d[t][1] = d[t][2] = d[t][3] = 0.f; }

    const unsigned* ah_base0 = g_a1h + (size_t)r0 * 32;
    const unsigned* ah_base1 = g_a1h + (size_t)(r0 + 8) * 32;
    const unsigned* al_base0 = g_a1l + (size_t)r0 * 32;
    const unsigned* al_base1 = g_a1l + (size_t)(r0 + 8) * 32;

#pragma unroll
    for (int ks = 0; ks < 4; ks++) {
        unsigned ah[4], al[4];
        ah[0] = __ldg(ah_base0 + ks * 8 + qid);
        ah[1] = __ldg(ah_base1 + ks * 8 + qid);
        ah[2] = __ldg(ah_base0 + ks * 8 + qid + 4);
        ah[3] = __ldg(ah_base1 + ks * 8 + qid + 4);
        al[0] = __ldg(al_base0 + ks * 8 + qid);
        al[1] = __ldg(al_base1 + ks * 8 + qid);
        al[2] = __ldg(al_base0 + ks * 8 + qid + 4);
        al[3] = __ldg(al_base1 + ks * 8 + qid + 4);
#pragma unroll
        for (int t = 0; t < 4; t++) {
            uint4 w = __ldg(&g_w2frag[(ks * 4 + t) * 32 + lane]);
            mma_bf16(d[t], ah, w.x, w.y);
            mma_bf16(d[t], al, w.x, w.y);
            mma_bf16(d[t], ah, w.z, w.w);
        }
    }

    float di0 = (r0 < n)     ? g_dinv[r0]     : 0.f;
    float di1 = (r0 + 8 < n) ? g_dinv[r0 + 8] : 0.f;
#pragma unroll
    for (int t = 0; t < 4; t++) {
        int col = t * 8 + qid * 2;
        if (r0 < n)     *(float2*)(g_h2 + (size_t)r0 * 32 + col)       = make_float2(di0 * d[t][0], di0 * d[t][1]);
        if (r0 + 8 < n) *(float2*)(g_h2 + (size_t)(r0 + 8) * 32 + col) = make_float2(di1 * d[t][2], di1 * d[t][3]);
    }
}

// ------- layer 2 agg fused with final linear ------------------------------------
__global__ __launch_bounds__(256) void k_agg2(const float* __restrict__ b2,
                                              const float* __restrict__ Wlin,
                                              const float* __restrict__ blin,
                                              float* __restrict__ out, int n) {
    int lane = threadIdx.x & 31;
    int node = (blockIdx.x * blockDim.x + threadIdx.x) >> 5;
    if (node >= n) return;

    float di = g_dinv[node];
    float acc0 = g_h2[(size_t)node * 32 + lane];   // self loop
    float acc1 = 0.f, acc2 = 0.f, acc3 = 0.f;

    const int* ep = g_srcfix + (size_t)node * DEGMAX;
    int cnt = g_cnt[node];
    if (cnt > DEGMAX) cnt = DEGMAX;
    int k = 0;
    for (; k + 16 <= cnt; k += 16) {
        int4 sa = *(const int4*)(ep + k);
        int4 sb = *(const int4*)(ep + k + 4);
        int4 sc = *(const int4*)(ep + k + 8);
        int4 sd = *(const int4*)(ep + k + 12);
        float v0  = g_h2[(size_t)sa.x * 32 + lane];
        float v1  = g_h2[(size_t)sa.y * 32 + lane];
        float v2  = g_h2[(size_t)sa.z * 32 + lane];
        float v3  = g_h2[(size_t)sa.w * 32 + lane];
        float v4  = g_h2[(size_t)sb.x * 32 + lane];
        float v5  = g_h2[(size_t)sb.y * 32 + lane];
        float v6  = g_h2[(size_t)sb.z * 32 + lane];
        float v7  = g_h2[(size_t)sb.w * 32 + lane];
        float v8  = g_h2[(size_t)sc.x * 32 + lane];
        float v9  = g_h2[(size_t)sc.y * 32 + lane];
        float v10 = g_h2[(size_t)sc.z * 32 + lane];
        float v11 = g_h2[(size_t)sc.w * 32 + lane];
        float v12 = g_h2[(size_t)sd.x * 32 + lane];
        float v13 = g_h2[(size_t)sd.y * 32 + lane];
        float v14 = g_h2[(size_t)sd.z * 32 + lane];
        float v15 = g_h2[(size_t)sd.w * 32 + lane];
        acc0 += v0 + v4 + v8  + v12;
        acc1 += v1 + v5 + v9  + v13;
        acc2 += v2 + v6 + v10 + v14;
        acc3 += v3 + v7 + v11 + v15;
    }
    for (; k + 8 <= cnt; k += 8) {
        int4 sa = *(const int4*)(ep + k);
        int4 sb = *(const int4*)(ep + k + 4);
        float v0 = g_h2[(size_t)sa.x * 32 + lane];
        float v1 = g_h2[(size_t)sa.y * 32 + lane];
        float v2 = g_h2[(size_t)sa.z * 32 + lane];
        float v3 = g_h2[(size_t)sa.w * 32 + lane];
        float v4 = g_h2[(size_t)sb.x * 32 + lane];
        float v5 = g_h2[(size_t)sb.y * 32 + lane];
        float v6 = g_h2[(size_t)sb.z * 32 + lane];
        float v7 = g_h2[(size_t)sb.w * 32 + lane];
        acc0 += v0 + v4; acc1 += v1 + v5; acc2 += v2 + v6; acc3 += v3 + v7;
    }
    for (; k < cnt; k++) {
        acc0 += g_h2[(size_t)ep[k] * 32 + lane];
    }
    acc0 += acc1 + acc2 + acc3;

    float v = fmaxf(fmaf(di, acc0, b2[lane]), 0.f);
    float p = v * Wlin[lane];
#pragma unroll
    for (int off = 16; off > 0; off >>= 1) p += __shfl_xor_sync(0xffffffffu, p, off);
    if (lane == 0) out[node] = p + blin[0];
}

// ---------------- launch -------------------------------------------------------
extern "C" void kernel_launch(void* const* d_in, const int* in_sizes, int n_in,
                              void* d_out, int out_size) {
    const float* x    = (const float*)d_in[0];
    const int*   ei   = (const int*)  d_in[1];
    const float* W1   = (const float*)d_in[2];
    const float* b1   = (const float*)d_in[3];
    const float* W2   = (const float*)d_in[4];
    const float* b2   = (const float*)d_in[5];
    const float* Wlin = (const float*)d_in[6];
    const float* blin = (const float*)d_in[7];
    float* out = (float*)d_out;

    int n = in_sizes[0] / 256;
    int e = in_sizes[1] / 2;
    if (n > NMAX) n = NMAX;
    if (e > EMAX) e = EMAX;
    const int* src = ei;
    const int* dst = ei + e;

    void* cnt_ptr = nullptr;
    cudaGetSymbolAddress(&cnt_ptr, g_cnt);
    cudaMemsetAsync(cnt_ptr, 0, (size_t)n * sizeof(int));

    // ncu window captures kernel slot 4 = k_agg1 (verify fp16-gather delta)
    k_fill_prep <<<(e + 255) / 256, 256>>>(src, dst, e, W1, W2);
    k_dinv      <<<(n + 255) / 256, 256>>>(n);
    k_gemm1     <<<(n + 63) / 64, 256>>>(x, n);
    k_agg1      <<<(n + 7) / 8, 256>>>(b1, n);
    k_gemm2t    <<<(n + 127) / 128, 256>>>(n);
    k_agg2      <<<(n + 7) / 8, 256>>>(b2, Wlin, blin, out, n);
}

// round 17
// speedup vs baseline: 1.1157x; 1.0468x over previous
#include <cuda_runtime.h>
#include <cuda_bf16.h>
#include <cuda_fp16.h>

#define NMAX 100000
#define NPAD 100128          // NMAX rounded up to 128-row block
#define EMAX 1600000
#define DEGMAX 64

// ---------------- scratch (device globals) -----------------------------------
__device__ int      g_cnt[NMAX];
__device__ float    g_dinv[NMAX];
__device__ int      g_srcfix[(size_t)NMAX * DEGMAX];  // per-dst src lists
__device__ unsigned g_h1[(size_t)NPAD * 32];          // dinv-scaled h1, fp16x2 pairs
__device__ unsigned g_a1h[(size_t)NPAD * 32];         // a1 bf16-hi packed pairs
__device__ unsigned g_a1l[(size_t)NPAD * 32];         // a1 bf16-lo packed pairs
__device__ unsigned g_h2f[(size_t)NPAD * 16];         // dinv-scaled h2, fp16x2 pairs
__device__ uint4    g_wfrag[4096];                    // W1 bf16 fragments
__device__ uint4    g_w2frag[512];                    // W2 bf16 fragments

// ---------------- helpers --------------------------------------------------------
__device__ __forceinline__ unsigned pack_bf16(__nv_bfloat16 lo, __nv_bfloat16 hi) {
    __nv_bfloat162 p; p.x = lo; p.y = hi;
    return *(unsigned*)&p;
}
__device__ __forceinline__ void split_bf16(float f, __nv_bfloat16& h, __nv_bfloat16& l) {
    h = __float2bfloat16_rn(f);
    l = __float2bfloat16_rn(f - __bfloat162float(h));
}
__device__ __forceinline__ unsigned pack_f16x2(float a, float b) {
    __half2 h = __float22half2_rn(make_float2(a, b));
    return *(unsigned*)&h;
}
__device__ __forceinline__ float2 unpack_f16x2(unsigned u) {
    __half2 h = *(__half2*)&u;
    return __half22float2(h);
}
__device__ __forceinline__ __half2 as_h2(unsigned u) { return *(__half2*)&u; }
__device__ __forceinline__ void mma_bf16(float* d, const unsigned* a, unsigned b0, unsigned b1) {
    asm volatile(
        "mma.sync.aligned.m16n8k16.row.col.f32.bf16.bf16.f32 "
        "{%0,%1,%2,%3}, {%4,%5,%6,%7}, {%8,%9}, {%0,%1,%2,%3};"
        : "+f"(d[0]), "+f"(d[1]), "+f"(d[2]), "+f"(d[3])
        : "r"(a[0]), "r"(a[1]), "r"(a[2]), "r"(a[3]), "r"(b0), "r"(b1));
}

// ---- build: bucket-fill src lists + fused W1/W2 fragment prep ------------------
__global__ void k_fill_prep(const int* __restrict__ src, const int* __restrict__ dst,
                            int e, const float* __restrict__ W1,
                            const float* __restrict__ W2) {
    int i = blockIdx.x * blockDim.x + threadIdx.x;
    if (i < 4096) {   // W1 fragments
        int lane = i & 31;
        int t    = (i >> 5) & 7;
        int ks   = i >> 8;
        int qid = lane & 3, grp = lane >> 2;
        int col = t * 8 + grp;
        int k0 = ks * 16 + qid * 2;
        float f00 = W1[k0 * 64 + col],       f01 = W1[(k0 + 1) * 64 + col];
        float f10 = W1[(k0 + 8) * 64 + col], f11 = W1[(k0 + 9) * 64 + col];
        __nv_bfloat16 h00, l00, h01, l01, h10, l10, h11, l11;
        split_bf16(f00, h00, l00); split_bf16(f01, h01, l01);
        split_bf16(f10, h10, l10); split_bf16(f11, h11, l11);
        g_wfrag[i] = make_uint4(pack_bf16(h00, h01), pack_bf16(h10, h11),
                                pack_bf16(l00, l01), pack_bf16(l10, l11));
    }
    if (i < 512) {    // W2 fragments
        int lane = i & 31;
        int t    = (i >> 5) & 3;
        int ks   = i >> 7;
        int qid = lane & 3, grp = lane >> 2;
        int col = t * 8 + grp;
        int k0 = ks * 16 + qid * 2;
        float f00 = W2[k0 * 32 + col],       f01 = W2[(k0 + 1) * 32 + col];
        float f10 = W2[(k0 + 8) * 32 + col], f11 = W2[(k0 + 9) * 32 + col];
        __nv_bfloat16 h00, l00, h01, l01, h10, l10, h11, l11;
        split_bf16(f00, h00, l00); split_bf16(f01, h01, l01);
        split_bf16(f10, h10, l10); split_bf16(f11, h11, l11);
        g_w2frag[i] = make_uint4(pack_bf16(h00, h01), pack_bf16(h10, h11),
                                 pack_bf16(l00, l01), pack_bf16(l10, l11));
    }
    if (i < e) {
        int s = src[i], d = dst[i];
        int pos = atomicAdd(&g_cnt[d], 1);
        if (pos < DEGMAX) g_srcfix[(size_t)d * DEGMAX + pos] = s;
    }
}

__global__ void k_dinv(int n) {
    int i = blockIdx.x * blockDim.x + threadIdx.x;
    if (i < n) g_dinv[i] = rsqrtf((float)(g_cnt[i] + 1));  // +1 self loop
}

// ------- layer 1 GEMM: ht1 = dinv * (x @ W1), bf16x3 m16n8k16 (R14/R16 proven) -
#define XS2 20
__global__ __launch_bounds__(256, 4) void k_gemm1(const float* __restrict__ x, int n) {
    __shared__ unsigned xhi[64 * XS2];
    __shared__ unsigned xlo[64 * XS2];
    int tid = threadIdx.x, lane = tid & 31, warp = tid >> 5;
    int node0 = blockIdx.x * 64;
    int grp = lane >> 2, qid = lane & 3;
    int rg = warp >> 1, cg = warp & 1;

    float d[4][4];
#pragma unroll
    for (int t = 0; t < 4; t++) { d[t][0] = d[t][1] = d[t][2] = d[t][3] = 0.f; }

    int srow = tid >> 2;
    int sq   = tid & 3;

    for (int kc = 0; kc < 8; kc++) {            // K chunk of 32
        __syncthreads();
        {
            float4 v0 = make_float4(0.f, 0.f, 0.f, 0.f);
            float4 v1 = make_float4(0.f, 0.f, 0.f, 0.f);
            if (node0 + srow < n) {
                const float4* xp = (const float4*)(x + (size_t)(node0 + srow) * 256 + kc * 32 + sq * 8);
                v0 = xp[0]; v1 = xp[1];
            }
            __nv_bfloat16 h0, l0, h1, l1;
            unsigned ph0, ph1, ph2, ph3, pl0, pl1, pl2, pl3;
            split_bf16(v0.x, h0, l0); split_bf16(v0.y, h1, l1);
            ph0 = pack_bf16(h0, h1); pl0 = pack_bf16(l0, l1);
            split_bf16(v0.z, h0, l0); split_bf16(v0.w, h1, l1);
            ph1 = pack_bf16(h0, h1); pl1 = pack_bf16(l0, l1);
            split_bf16(v1.x, h0, l0); split_bf16(v1.y, h1, l1);
            ph2 = pack_bf16(h0, h1); pl2 = pack_bf16(l0, l1);
            split_bf16(v1.z, h0, l0); split_bf16(v1.w, h1, l1);
            ph3 = pack_bf16(h0, h1); pl3 = pack_bf16(l0, l1);
            unsigned base = srow * XS2 + sq * 4;
            *(uint4*)(xhi + base) = make_uint4(ph0, ph1, ph2, ph3);
            *(uint4*)(xlo + base) = make_uint4(pl0, pl1, pl2, pl3);
        }
        __syncthreads();

#pragma unroll
        for (int ksl = 0; ksl < 2; ksl++) {
            int ks = kc * 2 + ksl;
            int r = rg * 16 + grp;
            int cb = ksl * 8;
            unsigned ah[4], al[4];
            ah[0] = xhi[r * XS2 + cb + qid];
            ah[1] = xhi[(r + 8) * XS2 + cb + qid];
            ah[2] = xhi[r * XS2 + cb + qid + 4];
            ah[3] = xhi[(r + 8) * XS2 + cb + qid + 4];
            al[0] = xlo[r * XS2 + cb + qid];
            al[1] = xlo[(r + 8) * XS2 + cb + qid];
            al[2] = xlo[r * XS2 + cb + qid + 4];
            al[3] = xlo[(r + 8) * XS2 + cb + qid + 4];
#pragma unroll
            for (int t = 0; t < 4; t++) {
                int tt = cg * 4 + t;
                uint4 w = __ldg(&g_wfrag[(ks * 8 + tt) * 32 + lane]);
                mma_bf16(d[t], ah, w.x, w.y);
                mma_bf16(d[t], al, w.x, w.y);
                mma_bf16(d[t], ah, w.z, w.w);
            }
        }
    }

    int r0 = node0 + rg * 16 + grp;
    float di0 = (r0 < n)     ? g_dinv[r0]     : 0.f;
    float di1 = (r0 + 8 < n) ? g_dinv[r0 + 8] : 0.f;
#pragma unroll
    for (int t = 0; t < 4; t++) {
        int j = cg * 16 + t * 4 + qid;   // fp16x2 word index (features 2j, 2j+1)
        if (r0 < n)     g_h1[(size_t)r0 * 32 + j]       = pack_f16x2(di0 * d[t][0], di0 * d[t][1]);
        if (r0 + 8 < n) g_h1[(size_t)(r0 + 8) * 32 + j] = pack_f16x2(di1 * d[t][2], di1 * d[t][3]);
    }
}

// ---- layer 1 aggregation: fp16x2 gather + pairwise HADD2 reduction -------------
__global__ __launch_bounds__(256) void k_agg1(const float* __restrict__ b1, int n) {
    int lane = threadIdx.x & 31;
    int node = (blockIdx.x * blockDim.x + threadIdx.x) >> 5;
    if (node >= n) return;

    float di = g_dinv[node];
    float2 acc0 = unpack_f16x2(g_h1[(size_t)node * 32 + lane]);  // self loop
    float2 acc1 = make_float2(0.f, 0.f);
    float2 acc2 = make_float2(0.f, 0.f);
    float2 acc3 = make_float2(0.f, 0.f);

    const int* ep = g_srcfix + (size_t)node * DEGMAX;
    int cnt = g_cnt[node];
    if (cnt > DEGMAX) cnt = DEGMAX;
    int k = 0;
    for (; k + 16 <= cnt; k += 16) {
        int4 sa = *(const int4*)(ep + k);
        int4 sb = *(const int4*)(ep + k + 4);
        int4 sc = *(const int4*)(ep + k + 8);
        int4 sd = *(const int4*)(ep + k + 12);
        unsigned u0  = g_h1[(size_t)sa.x * 32 + lane];
        unsigned u1  = g_h1[(size_t)sa.y * 32 + lane];
        unsigned u2  = g_h1[(size_t)sa.z * 32 + lane];
        unsigned u3  = g_h1[(size_t)sa.w * 32 + lane];
        unsigned u4  = g_h1[(size_t)sb.x * 32 + lane];
        unsigned u5  = g_h1[(size_t)sb.y * 32 + lane];
        unsigned u6  = g_h1[(size_t)sb.z * 32 + lane];
        unsigned u7  = g_h1[(size_t)sb.w * 32 + lane];
        unsigned u8  = g_h1[(size_t)sc.x * 32 + lane];
        unsigned u9  = g_h1[(size_t)sc.y * 32 + lane];
        unsigned u10 = g_h1[(size_t)sc.z * 32 + lane];
        unsigned u11 = g_h1[(size_t)sc.w * 32 + lane];
        unsigned u12 = g_h1[(size_t)sd.x * 32 + lane];
        unsigned u13 = g_h1[(size_t)sd.y * 32 + lane];
        unsigned u14 = g_h1[(size_t)sd.z * 32 + lane];
        unsigned u15 = g_h1[(size_t)sd.w * 32 + lane];
        // pairwise fp16 add (one HADD2 per 2 edges), then f32 accumulate
        float2 p0 = __half22float2(__hadd2(as_h2(u0), as_h2(u8)));
        float2 p1 = __half22float2(__hadd2(as_h2(u1), as_h2(u9)));
        float2 p2 = __half22float2(__hadd2(as_h2(u2), as_h2(u10)));
        float2 p3 = __half22float2(__hadd2(as_h2(u3), as_h2(u11)));
        float2 p4 = __half22float2(__hadd2(as_h2(u4), as_h2(u12)));
        float2 p5 = __half22float2(__hadd2(as_h2(u5), as_h2(u13)));
        float2 p6 = __half22float2(__hadd2(as_h2(u6), as_h2(u14)));
        float2 p7 = __half22float2(__hadd2(as_h2(u7), as_h2(u15)));
        acc0.x += p0.x; acc0.y += p0.y;
        acc1.x += p1.x; acc1.y += p1.y;
        acc2.x += p2.x; acc2.y += p2.y;
        acc3.x += p3.x; acc3.y += p3.y;
        acc0.x += p4.x; acc0.y += p4.y;
        acc1.x += p5.x; acc1.y += p5.y;
        acc2.x += p6.x; acc2.y += p6.y;
        acc3.x += p7.x; acc3.y += p7.y;
    }
    for (; k + 8 <= cnt; k += 8) {
        int4 sa = *(const int4*)(ep + k);
        int4 sb = *(const int4*)(ep + k + 4);
        unsigned u0 = g_h1[(size_t)sa.x * 32 + lane];
        unsigned u1 = g_h1[(size_t)sa.y * 32 + lane];
        unsigned u2 = g_h1[(size_t)sa.z * 32 + lane];
        unsigned u3 = g_h1[(size_t)sa.w * 32 + lane];
        unsigned u4 = g_h1[(size_t)sb.x * 32 + lane];
        unsigned u5 = g_h1[(size_t)sb.y * 32 + lane];
        unsigned u6 = g_h1[(size_t)sb.z * 32 + lane];
        unsigned u7 = g_h1[(size_t)sb.w * 32 + lane];
        float2 p0 = __half22float2(__hadd2(as_h2(u0), as_h2(u4)));
        float2 p1 = __half22float2(__hadd2(as_h2(u1), as_h2(u5)));
        float2 p2 = __half22float2(__hadd2(as_h2(u2), as_h2(u6)));
        float2 p3 = __half22float2(__hadd2(as_h2(u3), as_h2(u7)));
        acc0.x += p0.x; acc0.y += p0.y;
        acc1.x += p1.x; acc1.y += p1.y;
        acc2.x += p2.x; acc2.y += p2.y;
        acc3.x += p3.x; acc3.y += p3.y;
    }
    for (; k < cnt; k++) {
        float2 v = unpack_f16x2(g_h1[(size_t)ep[k] * 32 + lane]);
        acc0.x += v.x; acc0.y += v.y;
    }
    acc0.x += acc1.x + acc2.x + acc3.x;
    acc0.y += acc1.y + acc2.y + acc3.y;

    float2 bb = ((const float2*)b1)[lane];
    float ax = fmaxf(fmaf(di, acc0.x, bb.x), 0.f);
    float ay = fmaxf(fmaf(di, acc0.y, bb.y), 0.f);

    __nv_bfloat16 hx, lx, hy, ly;
    split_bf16(ax, hx, lx);
    split_bf16(ay, hy, ly);
    g_a1h[(size_t)node * 32 + lane] = pack_bf16(hx, hy);
    g_a1l[(size_t)node * 32 + lane] = pack_bf16(lx, ly);
}

// ---- layer 2 GEMM (tensor): ht2 = dinv * (a1 @ W2), fp16x2 output --------------
__global__ __launch_bounds__(256) void k_gemm2t(int n) {
    int tid = threadIdx.x, lane = tid & 31, warp = tid >> 5;
    int node0 = blockIdx.x * 128;
    int grp = lane >> 2, qid = lane & 3;
    int r0 = node0 + warp * 16 + grp;

    float d[4][4];
#pragma unroll
    for (int t = 0; t < 4; t++) { d[t][0] = d[t][1] = d[t][2] = d[t][3] = 0.f; }

    const unsigned* ah_base0 = g_a1h + (size_t)r0 * 32;
    const unsigned* ah_base1 = g_a1h + (size_t)(r0 + 8) * 32;
    const unsigned* al_base0 = g_a1l + (size_t)r0 * 32;
    const unsigned* al_base1 = g_a1l + (size_t)(r0 + 8) * 32;

#pragma unroll
    for (int ks = 0; ks < 4; ks++) {
        unsigned ah[4], al[4];
        ah[0] = __ldg(ah_base0 + ks * 8 + qid);
        ah[1] = __ldg(ah_base1 + ks * 8 + qid);
        ah[2] = __ldg(ah_base0 + ks * 8 + qid + 4);
        ah[3] = __ldg(ah_base1 + ks * 8 + qid + 4);
        al[0] = __ldg(al_base0 + ks * 8 + qid);
        al[1] = __ldg(al_base1 + ks * 8 + qid);
        al[2] = __ldg(al_base0 + ks * 8 + qid + 4);
        al[3] = __ldg(al_base1 + ks * 8 + qid + 4);
#pragma unroll
        for (int t = 0; t < 4; t++) {
            uint4 w = __ldg(&g_w2frag[(ks * 4 + t) * 32 + lane]);
            mma_bf16(d[t], ah, w.x, w.y);
            mma_bf16(d[t], al, w.x, w.y);
            mma_bf16(d[t], ah, w.z, w.w);
        }
    }

    float di0 = (r0 < n)     ? g_dinv[r0]     : 0.f;
    float di1 = (r0 + 8 < n) ? g_dinv[r0 + 8] : 0.f;
#pragma unroll
    for (int t = 0; t < 4; t++) {
        int j = t * 4 + qid;   // fp16x2 word index (features 2j, 2j+1), 0..15
        if (r0 < n)     g_h2f[(size_t)r0 * 16 + j]       = pack_f16x2(di0 * d[t][0], di0 * d[t][1]);
        if (r0 + 8 < n) g_h2f[(size_t)(r0 + 8) * 16 + j] = pack_f16x2(di1 * d[t][2], di1 * d[t][3]);
    }
}

// ------- layer 2 agg + final linear: fp16 gather, 2 edges per wavefront ---------
// Half-warp h (lane>>4) handles edges k+2j+h; lane&15 indexes the 16 fp16x2 words.
__global__ __launch_bounds__(256) void k_agg2(const float* __restrict__ b2,
                                              const float* __restrict__ Wlin,
                                              const float* __restrict__ blin,
                                              float* __restrict__ out, int n) {
    int lane = threadIdx.x & 31;
    int node = (blockIdx.x * blockDim.x + threadIdx.x) >> 5;
    if (node >= n) return;

    int h = lane >> 4;       // 0 or 1: which edge of each pair
    int w = lane & 15;       // fp16x2 word index

    float di = g_dinv[node];
    float2 acc0 = make_float2(0.f, 0.f);
    float2 acc1 = make_float2(0.f, 0.f);
    if (h == 0) acc0 = unpack_f16x2(g_h2f[(size_t)node * 16 + w]);  // self loop once

    const int* ep = g_srcfix + (size_t)node * DEGMAX;
    int cnt = g_cnt[node];
    if (cnt > DEGMAX) cnt = DEGMAX;
    int k = 0;
    for (; k + 8 <= cnt; k += 8) {
        int4 sa = *(const int4*)(ep + k);
        int4 sb = *(const int4*)(ep + k + 4);
        int s0 = h ? sa.y : sa.x;
        int s1 = h ? sa.w : sa.z;
        int s2 = h ? sb.y : sb.x;
        int s3 = h ? sb.w : sb.z;
        unsigned u0 = g_h2f[(size_t)s0 * 16 + w];
        unsigned u1 = g_h2f[(size_t)s1 * 16 + w];
        unsigned u2 = g_h2f[(size_t)s2 * 16 + w];
        unsigned u3 = g_h2f[(size_t)s3 * 16 + w];
        float2 p0 = __half22float2(__hadd2(as_h2(u0), as_h2(u1)));
        float2 p1 = __half22float2(__hadd2(as_h2(u2), as_h2(u3)));
        acc0.x += p0.x; acc0.y += p0.y;
        acc1.x += p1.x; acc1.y += p1.y;
    }
    for (; k < cnt; k += 2) {
        bool valid = (k + h) < cnt;
        unsigned u = 0;
        if (valid) u = g_h2f[(size_t)ep[k + h] * 16 + w];
        float2 v = unpack_f16x2(u);
        acc0.x += v.x; acc0.y += v.y;
    }
    acc0.x += acc1.x; acc0.y += acc1.y;

    // combine the two half-warps (each feature pair counted once per half)
    acc0.x += __shfl_xor_sync(0xffffffffu, acc0.x, 16);
    acc0.y += __shfl_xor_sync(0xffffffffu, acc0.y, 16);

    float2 bb = ((const float2*)b2)[w];
    float2 wl = ((const float2*)Wlin)[w];
    float vx = fmaxf(fmaf(di, acc0.x, bb.x), 0.f);
    float vy = fmaxf(fmaf(di, acc0.y, bb.y), 0.f);
    float p = vx * wl.x + vy * wl.y;
    // reduce over the 16 lanes of the low half (each feature pair once)
    p += __shfl_xor_sync(0xffffffffu, p, 8);
    p += __shfl_xor_sync(0xffffffffu, p, 4);
    p += __shfl_xor_sync(0xffffffffu, p, 2);
    p += __shfl_xor_sync(0xffffffffu, p, 1);
    if (lane == 0) out[node] = p + blin[0];
}

// ---------------- launch -------------------------------------------------------
extern "C" void kernel_launch(void* const* d_in, const int* in_sizes, int n_in,
                              void* d_out, int out_size) {
    const float* x    = (const float*)d_in[0];
    const int*   ei   = (const int*)  d_in[1];
    const float* W1   = (const float*)d_in[2];
    const float* b1   = (const float*)d_in[3];
    const float* W2   = (const float*)d_in[4];
    const float* b2   = (const float*)d_in[5];
    const float* Wlin = (const float*)d_in[6];
    const float* blin = (const float*)d_in[7];
    float* out = (float*)d_out;

    int n = in_sizes[0] / 256;
    int e = in_sizes[1] / 2;
    if (n > NMAX) n = NMAX;
    if (e > EMAX) e = EMAX;
    const int* src = ei;
    const int* dst = ei + e;

    void* cnt_ptr = nullptr;
    cudaGetSymbolAddress(&cnt_ptr, g_cnt);
    cudaMemsetAsync(cnt_ptr, 0, (size_t)n * sizeof(int));

    // ncu window captures kernel slot 4 = k_agg1 (verify HADD2-pairing delta)
    k_fill_prep <<<(e + 255) / 256, 256>>>(src, dst, e, W1, W2);
    k_dinv      <<<(n + 255) / 256, 256>>>(n);
    k_gemm1     <<<(n + 63) / 64, 256>>>(x, n);
    k_agg1      <<<(n + 7) / 8, 256>>>(b1, n);
    k_gemm2t    <<<(n + 127) / 128, 256>>>(n);
    k_agg2      <<<(n + 7) / 8, 256>>>(b2, Wlin, blin, out, n);
}